// round 13
// baseline (speedup 1.0000x reference)
#include <cuda_runtime.h>
#include <cuda_bf16.h>
#include <cuda_fp16.h>
#include <cuda_fp8.h>
#include <cstdint>

#define VOCAB 10000
#define EMBD 100
#define EMBP 128          // EMB padded to one full 128B chunk
#define SEQ 80
#define UNITS 512
#define BATCH 2048
#define BT (BATCH*SEQ)    // 163840

// fp8 scaling: keep values out of e4m3 subnormal range
#define HSCALE 256.0f
#define WSCALE 64.0f
#define DESCALE (1.0f/(HSCALE*WSCALE))

#define RGRIDX 8
#define RGRIDY 16

#define CH 128            // K bytes per chunk
#define AROW 144          // smem row pitch (128+16 pad, conflict-free ldmatrix)
#define ABUF (128*AROW)   // 18432 B
#define UROW 528          // U smem row pitch (512+16)
#define XW_SMEM (6*ABUF)              // 110592
#define R_SMEM (64*UROW + 4*ABUF)     // 107520

// ---------------- device scratch; t-major rows ----------------
__device__ __align__(16) uint8_t        g_X0[(size_t)BT * EMBP];   // fp8*HSCALE
__device__ __align__(16) uint8_t        g_X [(size_t)BT * UNITS];  // h, fp8*HSCALE
__device__ __align__(16) __nv_bfloat16  g_XW[(size_t)BT * UNITS];  // projection, bf16
__device__ __align__(16) uint8_t        g_W1t[UNITS * EMBP];       // W1^T fp8*WSCALE
__device__ __align__(16) uint8_t        g_Wt [3][UNITS * UNITS];
__device__ __align__(16) uint8_t        g_Ut [4][UNITS * UNITS];
// producer-pair flags: [layer][row group][t][chunk]; ready when == 2
__device__ unsigned g_bar[4][RGRIDY][SEQ][4];

// ---------------- PTX helpers ----------------
__device__ __forceinline__ uint32_t smaddr(const void* p) {
    return (uint32_t)__cvta_generic_to_shared(p);
}
__device__ __forceinline__ void cpa16(uint32_t dst, const void* src) {
    asm volatile("cp.async.cg.shared.global [%0], [%1], 16;\n" :: "r"(dst), "l"(src));
}
__device__ __forceinline__ void cp_commit() { asm volatile("cp.async.commit_group;\n"); }
template<int N> __device__ __forceinline__ void cp_wait() {
    asm volatile("cp.async.wait_group %0;\n" :: "n"(N));
}
__device__ __forceinline__ void ldsm4(uint32_t (&r)[4], uint32_t addr) {
    asm volatile("ldmatrix.sync.aligned.m8n8.x4.shared.b16 {%0,%1,%2,%3}, [%4];\n"
                 : "=r"(r[0]), "=r"(r[1]), "=r"(r[2]), "=r"(r[3]) : "r"(addr));
}
__device__ __forceinline__ void mma_fp8(float (&d)[4], const uint32_t (&a)[4],
                                        uint32_t b0, uint32_t b1) {
    asm volatile("mma.sync.aligned.m16n8k32.row.col.f32.e4m3.e4m3.f32 "
                 "{%0,%1,%2,%3}, {%4,%5,%6,%7}, {%8,%9}, {%0,%1,%2,%3};\n"
                 : "+f"(d[0]), "+f"(d[1]), "+f"(d[2]), "+f"(d[3])
                 : "r"(a[0]), "r"(a[1]), "r"(a[2]), "r"(a[3]), "r"(b0), "r"(b1));
}
__device__ __forceinline__ uint8_t to_fp8(float v) {
    return (uint8_t)__nv_cvt_float_to_fp8(v, __NV_SATFINITE, __NV_E4M3);
}
// fast tanh: 1 - 2/(e^{2x}+1); saturates to +-1 for large |x| (no NaN)
__device__ __forceinline__ float ftanh(float x) {
    return 1.0f - __fdividef(2.0f, __expf(2.0f * x) + 1.0f);
}

// ---------------- prep kernels (2 launches; rnn L1 stays at ncu's launch #4) -----
__global__ void cvtAll_kernel(
    const float* __restrict__ W1, const float* __restrict__ W2,
    const float* __restrict__ W3, const float* __restrict__ W4,
    const float* __restrict__ U1, const float* __restrict__ U2,
    const float* __restrict__ U3, const float* __restrict__ U4)
{
    int i = blockIdx.x * blockDim.x + threadIdx.x;
    if (i < 512 * 128) {
        int n = i >> 7, k = i & 127;
        g_W1t[i] = to_fp8(k < EMBD ? W1[(size_t)k * 512 + n] * WSCALE : 0.0f);
        return;
    }
    i -= 512 * 128;
    if (i < 3 * 512 * 512) {
        int m = i >> 18, r = i & (512 * 512 - 1);
        int n = r >> 9, k = r & 511;
        const float* Wm = (m == 0) ? W2 : (m == 1) ? W3 : W4;
        g_Wt[m][r] = to_fp8(Wm[(size_t)k * 512 + n] * WSCALE);
        return;
    }
    i -= 3 * 512 * 512;
    if (i >= 4 * 512 * 512) return;
    int m = i >> 18, r = i & (512 * 512 - 1);
    int n = r >> 9, k = r & 511;
    const float* Um = (m == 0) ? U1 : (m == 1) ? U2 : (m == 2) ? U3 : U4;
    g_Ut[m][r] = to_fp8(Um[(size_t)k * 512 + n] * WSCALE);
}

__global__ void embed_zero_kernel(const int* __restrict__ tokens,
                                  const float* __restrict__ emb) {
    int i = blockIdx.x * blockDim.x + threadIdx.x;
    if (i < 4 * RGRIDY * SEQ * 4) ((unsigned*)g_bar)[i] = 0u;
    if (i >= BT * EMBP) return;
    int r = i >> 7, k = i & 127;
    int t = r / BATCH, b = r - t * BATCH;
    float v = (k < EMBD) ? emb[(size_t)tokens[b * SEQ + t] * EMBD + k] * HSCALE : 0.0f;
    g_X0[i] = to_fp8(v);
}

// ================= XW GEMM (fp8): C = (A @ Bt^T)*DESCALE + bias, bf16 out =======
__global__ __launch_bounds__(256, 1) void gemm_fp8(
    const uint8_t* __restrict__ A, int lda,
    const uint8_t* __restrict__ Bt, int ldb,
    const float* __restrict__ bias,
    __nv_bfloat16* __restrict__ C, int nchunk)
{
    extern __shared__ __align__(128) uint8_t smbuf[];
    const uint32_t sb = smaddr(smbuf);
    const uint32_t BOFF = 3 * ABUF;

    const int tid = threadIdx.x, lane = tid & 31, wid = tid >> 5;
    const int wm = wid & 3, wn = wid >> 2;
    const int rowBase = blockIdx.y * 128, colBase = blockIdx.x * 128;

    auto loadAB = [&](int c) {
        const int buf = c % 3;
        const uint8_t* Ab = A  + (size_t)rowBase * lda + c * CH;
        const uint8_t* Bb = Bt + (size_t)colBase * ldb + c * CH;
        #pragma unroll
        for (int i = 0; i < 4; i++) {
            int u = tid + i * 256;
            int row = u >> 3, c16 = (u & 7) * 16;
            cpa16(sb + buf * ABUF + row * AROW + c16, Ab + (size_t)row * lda + c16);
            cpa16(sb + BOFF + buf * ABUF + row * AROW + c16, Bb + (size_t)row * ldb + c16);
        }
        cp_commit();
    };

    loadAB(0);
    if (nchunk > 1) loadAB(1);

    float acc[2][8][4];
    #pragma unroll
    for (int mt = 0; mt < 2; mt++)
        #pragma unroll
        for (int nf = 0; nf < 8; nf++)
            #pragma unroll
            for (int j = 0; j < 4; j++) acc[mt][nf][j] = 0.0f;

    for (int c = 0; c < nchunk; ++c) {
        if (c + 1 < nchunk) cp_wait<1>(); else cp_wait<0>();
        __syncthreads();
        if (c + 2 < nchunk) loadAB(c + 2);
        const uint32_t sa  = sb + (c % 3) * ABUF;
        const uint32_t sbb = sb + BOFF + (c % 3) * ABUF;
        #pragma unroll
        for (int k = 0; k < 4; k++) {
            uint32_t a[2][4];
            #pragma unroll
            for (int mt = 0; mt < 2; mt++)
                ldsm4(a[mt], sa + (uint32_t)(wm * 32 + mt * 16 + (lane & 15)) * AROW
                                + k * 32 + ((lane >> 4) << 4));
            #pragma unroll
            for (int g = 0; g < 4; g++) {
                uint32_t b[4];
                ldsm4(b, sbb + (uint32_t)(wn * 64 + g * 16 + (lane & 7)
                                          + ((lane >> 4) << 3)) * AROW
                             + k * 32 + (((lane >> 3) & 1) << 4));
                mma_fp8(acc[0][2 * g],     a[0], b[0], b[1]);
                mma_fp8(acc[1][2 * g],     a[1], b[0], b[1]);
                mma_fp8(acc[0][2 * g + 1], a[0], b[2], b[3]);
                mma_fp8(acc[1][2 * g + 1], a[1], b[2], b[3]);
            }
        }
        __syncthreads();
    }

    const int r0 = rowBase + wm * 32 + (lane >> 2);
    const int c0 = colBase + wn * 64 + (lane & 3) * 2;
    #pragma unroll
    for (int mt = 0; mt < 2; mt++)
        #pragma unroll
        for (int nf = 0; nf < 8; nf++) {
            int r = r0 + mt * 16, c = c0 + nf * 8;
            float b0 = bias[c], b1 = bias[c + 1];
            __nv_bfloat162 v0 = __float22bfloat162_rn(
                make_float2(acc[mt][nf][0] * DESCALE + b0, acc[mt][nf][1] * DESCALE + b1));
            __nv_bfloat162 v1 = __float22bfloat162_rn(
                make_float2(acc[mt][nf][2] * DESCALE + b0, acc[mt][nf][3] * DESCALE + b1));
            *(__nv_bfloat162*)(C + (size_t)r * UNITS + c)       = v0;
            *(__nv_bfloat162*)(C + (size_t)(r + 8) * UNITS + c) = v1;
        }
}

// ================= persistent recurrence (fp8, 512 threads, pair-flag dataflow) ==
// grid (8,16)=128 CTAs, 1/SM. CTA (x,y): rows [128y..), cols [64x..). U resident.
// Chunk c of h_{t-1} is produced by col-CTAs {2c,2c+1} only -> per-chunk flags.
// Each CTA consumes chunks in rotated order starting at its own pair, so the first
// poll is (nearly) free and producer skew is absorbed instead of accumulated.
__global__ __launch_bounds__(512, 1) void rnn_fp8(
    const uint8_t* __restrict__ Ut,
    const __nv_bfloat16* __restrict__ XW,
    uint8_t* __restrict__ X,
    int layer)
{
    extern __shared__ __align__(128) uint8_t smbuf[];
    const uint32_t sb = smaddr(smbuf);
    const uint32_t AOFF = 64 * UROW;

    const int tid = threadIdx.x, lane = tid & 31, wid = tid >> 5;
    const int wm = wid & 7, wn = wid >> 3;
    const int rowBase = blockIdx.y * 128, colBase = blockIdx.x * 64;
    const int pair = blockIdx.x >> 1;

    // resident U slice [64 n][512 k]
    #pragma unroll
    for (int i = 0; i < 4; i++) {
        int u = tid + i * 512;
        int row = u >> 5, c16 = (u & 31) * 16;
        cpa16(sb + (uint32_t)row * UROW + c16, Ut + (size_t)(colBase + row) * UNITS + c16);
    }
    cp_commit();
    cp_wait<0>();
    __syncthreads();

    const int r0 = rowBase + wm * 16 + (lane >> 2);
    const int c0 = colBase + wn * 32 + (lane & 3) * 2;

    // loop-invariant addresses
    const uint32_t aBase = sb + AOFF + (uint32_t)(wm * 16 + (lane & 15)) * AROW
                         + ((lane >> 4) << 4);
    const uint32_t bRow0 = (uint32_t)(wn * 32 + (lane & 7) + ((lane >> 4) << 3));
    const uint32_t bBase = sb + (((lane >> 3) & 1) << 4);
    const uint32_t ldRow = (tid >> 3), ldCol = (tid & 7) * 16;

    // poll chunk flag (>=2 producers), then issue this CTA's share of the load
    auto pollload = [&](int t, int slot) {
        const int chunk = (pair + slot) & 3;
        unsigned* f = &g_bar[layer][blockIdx.y][t - 1][chunk];
        if (lane == 0) {
            unsigned v;
            do {
                asm volatile("ld.acquire.gpu.global.u32 %0, [%1];"
                             : "=r"(v) : "l"(f) : "memory");
            } while (v < 2u);
        }
        __syncwarp();
        const uint8_t* Ab = X + ((size_t)(t - 1) * BATCH + rowBase) * UNITS + chunk * CH;
        #pragma unroll
        for (int i = 0; i < 2; i++) {
            uint32_t row = ldRow + i * 64;
            cpa16(sb + AOFF + slot * ABUF + row * AROW + ldCol,
                  Ab + (size_t)row * UNITS + ldCol);
        }
        cp_commit();
    };

    for (int t = 0; t < SEQ; ++t) {
        if (t > 0) { pollload(t, 0); pollload(t, 1); }

        // XW fragment prefetch
        uint32_t xwv[4][2];
        #pragma unroll
        for (int nf = 0; nf < 4; nf++) {
            size_t base = ((size_t)t * BATCH + r0) * UNITS + c0 + nf * 8;
            xwv[nf][0] = *(const uint32_t*)(XW + base);
            xwv[nf][1] = *(const uint32_t*)(XW + base + 8 * UNITS);
        }

        float acc[4][4];
        #pragma unroll
        for (int nf = 0; nf < 4; nf++)
            #pragma unroll
            for (int j = 0; j < 4; j++) acc[nf][j] = 0.0f;

        if (t > 0) {
            #pragma unroll
            for (int slot = 0; slot < 4; slot++) {
                if (slot < 3) cp_wait<1>(); else cp_wait<0>();
                __syncthreads();
                if (slot < 2) pollload(t, slot + 2);   // overlap with this slot's mma
                const int chunk = (pair + slot) & 3;
                #pragma unroll
                for (int k = 0; k < 4; k++) {
                    uint32_t a[4];
                    ldsm4(a, aBase + slot * ABUF + k * 32);
                    #pragma unroll
                    for (int g = 0; g < 2; g++) {
                        uint32_t b[4];
                        ldsm4(b, bBase + (bRow0 + g * 16) * UROW + chunk * CH + k * 32);
                        mma_fp8(acc[2 * g],     a, b[0], b[1]);
                        mma_fp8(acc[2 * g + 1], a, b[2], b[3]);
                    }
                }
            }
        }

        // epilogue: h = tanh(acc*DESCALE + XW); store fp8*HSCALE
        #pragma unroll
        for (int nf = 0; nf < 4; nf++) {
            float2 xa = __bfloat1622float2(*(__nv_bfloat162*)&xwv[nf][0]);
            float2 xb = __bfloat1622float2(*(__nv_bfloat162*)&xwv[nf][1]);
            float p0 = ftanh(acc[nf][0] * DESCALE + xa.x);
            float p1 = ftanh(acc[nf][1] * DESCALE + xa.y);
            float p2 = ftanh(acc[nf][2] * DESCALE + xb.x);
            float p3 = ftanh(acc[nf][3] * DESCALE + xb.y);
            size_t base = ((size_t)t * BATCH + r0) * UNITS + c0 + nf * 8;
            *(unsigned short*)(X + base) =
                __nv_cvt_float2_to_fp8x2(make_float2(p0 * HSCALE, p1 * HSCALE),
                                         __NV_SATFINITE, __NV_E4M3);
            *(unsigned short*)(X + base + 8 * UNITS) =
                __nv_cvt_float2_to_fp8x2(make_float2(p2 * HSCALE, p3 * HSCALE),
                                         __NV_SATFINITE, __NV_E4M3);
        }

        // producer arrival: stores visible (syncthreads), then release-add own pair
        if (t < SEQ - 1) {
            __syncthreads();
            if (tid == 0) {
                unsigned* f = &g_bar[layer][blockIdx.y][t][pair];
                asm volatile("red.release.gpu.global.add.u32 [%0], %1;"
                             :: "l"(f), "r"(1u) : "memory");
            }
        }
    }
}

// ---------------- head ----------------
__global__ void final_kernel(const uint8_t* __restrict__ X,
                             const float* __restrict__ Wo, const float* __restrict__ bo,
                             float* __restrict__ out) {
    int gw   = (blockIdx.x * blockDim.x + threadIdx.x) >> 5;
    int lane = threadIdx.x & 31;
    if (gw >= BATCH) return;
    const uint8_t* h = X + ((size_t)(SEQ - 1) * BATCH + gw) * UNITS;
    float s = 0.0f;
    for (int k = lane; k < UNITS; k += 32) {
        __half_raw hr = __nv_cvt_fp8_to_halfraw(h[k], __NV_E4M3);
        s += __half2float(*(__half*)&hr) * Wo[k];
    }
    #pragma unroll
    for (int o = 16; o; o >>= 1) s += __shfl_xor_sync(0xffffffffu, s, o);
    if (lane == 0) out[gw] = 1.0f / (1.0f + expf(-(s * (1.0f / HSCALE) + bo[0])));
}

// ---------------- host ----------------
extern "C" void kernel_launch(void* const* d_in, const int* in_sizes, int n_in,
                              void* d_out, int out_size) {
    const int*   tokens = (const int*)d_in[0];
    const float* emb    = (const float*)d_in[1];
    const float* W[4]  = {(const float*)d_in[2], (const float*)d_in[5],
                          (const float*)d_in[8], (const float*)d_in[11]};
    const float* U[4]  = {(const float*)d_in[3], (const float*)d_in[6],
                          (const float*)d_in[9], (const float*)d_in[12]};
    const float* bv[4] = {(const float*)d_in[4], (const float*)d_in[7],
                          (const float*)d_in[10], (const float*)d_in[13]};
    const float* Wo = (const float*)d_in[14];
    const float* bo = (const float*)d_in[15];
    float* out = (float*)d_out;

    uint8_t *X0p, *Xp, *W1tp, *Wtp, *Utp;
    __nv_bfloat16* XWp;
    cudaGetSymbolAddress((void**)&X0p,  g_X0);
    cudaGetSymbolAddress((void**)&Xp,   g_X);
    cudaGetSymbolAddress((void**)&XWp,  g_XW);
    cudaGetSymbolAddress((void**)&W1tp, g_W1t);
    cudaGetSymbolAddress((void**)&Wtp,  g_Wt);
    cudaGetSymbolAddress((void**)&Utp,  g_Ut);

    cudaFuncSetAttribute(gemm_fp8, cudaFuncAttributeMaxDynamicSharedMemorySize, XW_SMEM);
    cudaFuncSetAttribute(rnn_fp8,  cudaFuncAttributeMaxDynamicSharedMemorySize, R_SMEM);

    // launch #1, #2: prep (launch #3 = gemm L1, launch #4 = rnn L1 for ncu)
    cvtAll_kernel<<<(512*128 + 7*512*512 + 255) / 256, 256>>>(
        W[0], W[1], W[2], W[3], U[0], U[1], U[2], U[3]);
    embed_zero_kernel<<<(BT * EMBP + 255) / 256, 256>>>(tokens, emb);

    for (int l = 0; l < 4; l++) {
        if (l == 0) {
            gemm_fp8<<<dim3(UNITS / 128, BT / 128), 256, XW_SMEM>>>(
                X0p, EMBP, W1tp, EMBP, bv[0], XWp, 1);
        } else {
            gemm_fp8<<<dim3(UNITS / 128, BT / 128), 256, XW_SMEM>>>(
                Xp, UNITS, Wtp + (size_t)(l - 1) * UNITS * UNITS, UNITS,
                bv[l], XWp, 4);
        }
        rnn_fp8<<<dim3(RGRIDX, RGRIDY), 512, R_SMEM>>>(
            Utp + (size_t)l * UNITS * UNITS, XWp, Xp, l);
    }

    final_kernel<<<BATCH / 8, 256>>>(Xp, Wo, bo, out);
}

// round 15
// speedup vs baseline: 1.2232x; 1.2232x over previous
#include <cuda_runtime.h>
#include <cuda_bf16.h>
#include <cuda_fp16.h>
#include <cuda_fp8.h>
#include <cstdint>

#define VOCAB 10000
#define EMBD 100
#define EMBP 128          // EMB padded to one full 128B chunk
#define SEQ 80
#define UNITS 512
#define BATCH 2048
#define BT (BATCH*SEQ)    // 163840

// fp8 scaling: keep values out of e4m3 subnormal range
#define HSCALE 256.0f
#define WSCALE 64.0f
#define DESCALE (1.0f/(HSCALE*WSCALE))

#define CH 128
#define AROW 144          // gemm smem row pitch
#define ABUF (128*AROW)
#define XW_SMEM (6*ABUF)  // 110592

// rnn cluster kernel: 128 CTAs = 64 clusters x 2. CTA: 32 rows, 256 n-cols, K=512.
#define UROW 528                         // 512 + 16 pad
#define RU_BYTES (256*UROW)              // 135168 resident U half
#define RABUF (32*UROW)                  // 16896 per A buffer
#define SB_A RU_BYTES
#define SB_MBAR (SB_A + 2*RABUF)         // 168960
#define R_SMEM (SB_MBAR + 64)

// ---------------- device scratch; t-major rows ----------------
__device__ __align__(16) uint8_t        g_X0[(size_t)BT * EMBP];   // fp8*HSCALE
__device__ __align__(16) uint8_t        g_X [(size_t)BT * UNITS];  // h, fp8*HSCALE
__device__ __align__(16) __nv_bfloat16  g_XW[(size_t)BT * UNITS];  // projection, bf16
__device__ __align__(16) uint8_t        g_W1t[UNITS * EMBP];       // W1^T fp8*WSCALE
__device__ __align__(16) uint8_t        g_Wt [3][UNITS * UNITS];
__device__ __align__(16) uint8_t        g_Ut [4][UNITS * UNITS];

// ---------------- PTX helpers ----------------
__device__ __forceinline__ uint32_t smaddr(const void* p) {
    return (uint32_t)__cvta_generic_to_shared(p);
}
__device__ __forceinline__ void cpa16(uint32_t dst, const void* src) {
    asm volatile("cp.async.cg.shared.global [%0], [%1], 16;\n" :: "r"(dst), "l"(src));
}
__device__ __forceinline__ void cp_commit() { asm volatile("cp.async.commit_group;\n"); }
template<int N> __device__ __forceinline__ void cp_wait() {
    asm volatile("cp.async.wait_group %0;\n" :: "n"(N));
}
__device__ __forceinline__ void ldsm4(uint32_t (&r)[4], uint32_t addr) {
    asm volatile("ldmatrix.sync.aligned.m8n8.x4.shared.b16 {%0,%1,%2,%3}, [%4];\n"
                 : "=r"(r[0]), "=r"(r[1]), "=r"(r[2]), "=r"(r[3]) : "r"(addr));
}
__device__ __forceinline__ void mma_fp8(float (&d)[4], const uint32_t (&a)[4],
                                        uint32_t b0, uint32_t b1) {
    asm volatile("mma.sync.aligned.m16n8k32.row.col.f32.e4m3.e4m3.f32 "
                 "{%0,%1,%2,%3}, {%4,%5,%6,%7}, {%8,%9}, {%0,%1,%2,%3};\n"
                 : "+f"(d[0]), "+f"(d[1]), "+f"(d[2]), "+f"(d[3])
                 : "r"(a[0]), "r"(a[1]), "r"(a[2]), "r"(a[3]), "r"(b0), "r"(b1));
}
__device__ __forceinline__ uint8_t to_fp8(float v) {
    return (uint8_t)__nv_cvt_float_to_fp8(v, __NV_SATFINITE, __NV_E4M3);
}
__device__ __forceinline__ float ftanh(float x) {
    return 1.0f - __fdividef(2.0f, __expf(2.0f * x) + 1.0f);
}
#define MBAR_INIT(mb, c) asm volatile("mbarrier.init.shared.b64 [%0], %1;" :: "r"(mb), "r"(c) : "memory")

__device__ __forceinline__ void mbar_wait_cluster(uint32_t mb, uint32_t parity) {
    asm volatile(
        "{\n .reg .pred P;\n"
        "L1_%=:\n"
        " mbarrier.try_wait.parity.acquire.cluster.shared::cta.b64 P, [%0], %1, 0x989680;\n"
        " @P bra.uni L2_%=;\n"
        " bra.uni L1_%=;\n"
        "L2_%=:\n}"
        :: "r"(mb), "r"(parity) : "memory");
}

// ---------------- prep kernels (2 launches; rnn L1 stays at ncu's launch #4) -----
__global__ void cvtAll_kernel(
    const float* __restrict__ W1, const float* __restrict__ W2,
    const float* __restrict__ W3, const float* __restrict__ W4,
    const float* __restrict__ U1, const float* __restrict__ U2,
    const float* __restrict__ U3, const float* __restrict__ U4)
{
    int i = blockIdx.x * blockDim.x + threadIdx.x;
    if (i < 512 * 128) {
        int n = i >> 7, k = i & 127;
        g_W1t[i] = to_fp8(k < EMBD ? W1[(size_t)k * 512 + n] * WSCALE : 0.0f);
        return;
    }
    i -= 512 * 128;
    if (i < 3 * 512 * 512) {
        int m = i >> 18, r = i & (512 * 512 - 1);
        int n = r >> 9, k = r & 511;
        const float* Wm = (m == 0) ? W2 : (m == 1) ? W3 : W4;
        g_Wt[m][r] = to_fp8(Wm[(size_t)k * 512 + n] * WSCALE);
        return;
    }
    i -= 3 * 512 * 512;
    if (i >= 4 * 512 * 512) return;
    int m = i >> 18, r = i & (512 * 512 - 1);
    int n = r >> 9, k = r & 511;
    const float* Um = (m == 0) ? U1 : (m == 1) ? U2 : (m == 2) ? U3 : U4;
    g_Ut[m][r] = to_fp8(Um[(size_t)k * 512 + n] * WSCALE);
}

__global__ void embed_kernel(const int* __restrict__ tokens,
                             const float* __restrict__ emb) {
    int i = blockIdx.x * blockDim.x + threadIdx.x;
    if (i >= BT * EMBP) return;
    int r = i >> 7, k = i & 127;
    int t = r / BATCH, b = r - t * BATCH;
    float v = (k < EMBD) ? emb[(size_t)tokens[b * SEQ + t] * EMBD + k] * HSCALE : 0.0f;
    g_X0[i] = to_fp8(v);
}

// ================= XW GEMM (fp8): C = (A @ Bt^T)*DESCALE + bias, bf16 out =======
__global__ __launch_bounds__(256, 1) void gemm_fp8(
    const uint8_t* __restrict__ A, int lda,
    const uint8_t* __restrict__ Bt, int ldb,
    const float* __restrict__ bias,
    __nv_bfloat16* __restrict__ C, int nchunk)
{
    extern __shared__ __align__(128) uint8_t smbuf[];
    const uint32_t sb = smaddr(smbuf);
    const uint32_t BOFF = 3 * ABUF;

    const int tid = threadIdx.x, lane = tid & 31, wid = tid >> 5;
    const int wm = wid & 3, wn = wid >> 2;
    const int rowBase = blockIdx.y * 128, colBase = blockIdx.x * 128;

    auto loadAB = [&](int c) {
        const int buf = c % 3;
        const uint8_t* Ab = A  + (size_t)rowBase * lda + c * CH;
        const uint8_t* Bb = Bt + (size_t)colBase * ldb + c * CH;
        #pragma unroll
        for (int i = 0; i < 4; i++) {
            int u = tid + i * 256;
            int row = u >> 3, c16 = (u & 7) * 16;
            cpa16(sb + buf * ABUF + row * AROW + c16, Ab + (size_t)row * lda + c16);
            cpa16(sb + BOFF + buf * ABUF + row * AROW + c16, Bb + (size_t)row * ldb + c16);
        }
        cp_commit();
    };

    loadAB(0);
    if (nchunk > 1) loadAB(1);

    float acc[2][8][4];
    #pragma unroll
    for (int mt = 0; mt < 2; mt++)
        #pragma unroll
        for (int nf = 0; nf < 8; nf++)
            #pragma unroll
            for (int j = 0; j < 4; j++) acc[mt][nf][j] = 0.0f;

    for (int c = 0; c < nchunk; ++c) {
        if (c + 1 < nchunk) cp_wait<1>(); else cp_wait<0>();
        __syncthreads();
        if (c + 2 < nchunk) loadAB(c + 2);
        const uint32_t sa  = sb + (c % 3) * ABUF;
        const uint32_t sbb = sb + BOFF + (c % 3) * ABUF;
        #pragma unroll
        for (int k = 0; k < 4; k++) {
            uint32_t a[2][4];
            #pragma unroll
            for (int mt = 0; mt < 2; mt++)
                ldsm4(a[mt], sa + (uint32_t)(wm * 32 + mt * 16 + (lane & 15)) * AROW
                                + k * 32 + ((lane >> 4) << 4));
            #pragma unroll
            for (int g = 0; g < 4; g++) {
                uint32_t b[4];
                ldsm4(b, sbb + (uint32_t)(wn * 64 + g * 16 + (lane & 7)
                                          + ((lane >> 4) << 3)) * AROW
                             + k * 32 + (((lane >> 3) & 1) << 4));
                mma_fp8(acc[0][2 * g],     a[0], b[0], b[1]);
                mma_fp8(acc[1][2 * g],     a[1], b[0], b[1]);
                mma_fp8(acc[0][2 * g + 1], a[0], b[2], b[3]);
                mma_fp8(acc[1][2 * g + 1], a[1], b[2], b[3]);
            }
        }
        __syncthreads();
    }

    const int r0 = rowBase + wm * 32 + (lane >> 2);
    const int c0 = colBase + wn * 64 + (lane & 3) * 2;
    #pragma unroll
    for (int mt = 0; mt < 2; mt++)
        #pragma unroll
        for (int nf = 0; nf < 8; nf++) {
            int r = r0 + mt * 16, c = c0 + nf * 8;
            float b0 = bias[c], b1 = bias[c + 1];
            __nv_bfloat162 v0 = __float22bfloat162_rn(
                make_float2(acc[mt][nf][0] * DESCALE + b0, acc[mt][nf][1] * DESCALE + b1));
            __nv_bfloat162 v1 = __float22bfloat162_rn(
                make_float2(acc[mt][nf][2] * DESCALE + b0, acc[mt][nf][3] * DESCALE + b1));
            *(__nv_bfloat162*)(C + (size_t)r * UNITS + c)       = v0;
            *(__nv_bfloat162*)(C + (size_t)(r + 8) * UNITS + c) = v1;
        }
}

// ================= persistent recurrence: 2-CTA clusters, DSMEM h-exchange ======
// 128 CTAs = 64 clusters. Cluster: 32 batch rows. CTA rank r: n-cols [256r,256r+256),
// U half [256 n][512 k] SMEM-resident. h exchange: own half -> own smem A-buf (STS),
// peer half arrives via st.shared::cluster. Double-buffered by step parity + 2 mbarriers.
// Own-half mma runs BEFORE the mbarrier wait (hides peer skew + store drain).
__global__ __launch_bounds__(512, 1) __cluster_dims__(2, 1, 1)
void rnn_fp8(const uint8_t* __restrict__ Ut,
             const __nv_bfloat16* __restrict__ XW,
             uint8_t* __restrict__ X, int layer)
{
    extern __shared__ __align__(128) uint8_t smbuf[];
    const uint32_t sb = smaddr(smbuf);

    const int tid = threadIdx.x, lane = tid & 31, wid = tid >> 5;
    const int wm = wid & 1, wn = wid >> 1;            // 2 m-strips x 8 n-strips
    const int rank = blockIdx.x & 1;
    const int rowBase = (blockIdx.x >> 1) * 32;
    const int colBase = rank * 256;                   // n-range AND own k-half

    // resident U half [256 n][512 k]
    #pragma unroll
    for (int i = 0; i < 16; i++) {
        int u = tid + i * 512;
        int row = u >> 5, c16 = (u & 31) * 16;
        cpa16(sb + (uint32_t)row * UROW + c16, Ut + (size_t)(colBase + row) * UNITS + c16);
    }
    cp_commit(); cp_wait<0>();

    if (tid == 0) {
        MBAR_INIT(sb + SB_MBAR + 0, 2);
        MBAR_INIT(sb + SB_MBAR + 8, 2);
    }
    __syncthreads();
    asm volatile("barrier.cluster.arrive.aligned;" ::: "memory");
    asm volatile("barrier.cluster.wait.aligned;" ::: "memory");

    uint32_t peerSb;
    asm("mapa.shared::cluster.u32 %0, %1, %2;" : "=r"(peerSb) : "r"(sb), "r"(1 - rank));

    const int r0l = wm * 16 + (lane >> 2);            // local row 0..31 (and +8)
    const int c0l = wn * 32 + (lane & 3) * 2;         // local n col 0..255
    const uint32_t aFragRow = sb + SB_A + (uint32_t)(wm * 16 + (lane & 15)) * UROW
                            + ((lane >> 4) << 4);
    const uint32_t bRow0 = (uint32_t)(wn * 32 + (lane & 7) + ((lane >> 4) << 3));
    const uint32_t bBase = sb + (((lane >> 3) & 1) << 4);
    const int kOwn  = colBase;                        // k bytes this CTA produced
    const int kPeer = 256 - colBase;

    for (int t = 0; t < SEQ; ++t) {
        // XW prefetch (latency hidden under mma)
        uint32_t xwv[4][2];
        #pragma unroll
        for (int nf = 0; nf < 4; nf++) {
            size_t base = ((size_t)t * BATCH + rowBase + r0l) * UNITS + colBase + c0l + nf * 8;
            xwv[nf][0] = *(const uint32_t*)(XW + base);
            xwv[nf][1] = *(const uint32_t*)(XW + base + 8 * UNITS);
        }

        float acc[4][4];
        #pragma unroll
        for (int nf = 0; nf < 4; nf++)
            #pragma unroll
            for (int j = 0; j < 4; j++) acc[nf][j] = 0.0f;

        if (t > 0) {
            const uint32_t aOff = (uint32_t)(t & 1) * RABUF;
            // own k-half first: locally produced, ordered by last step's syncthreads
            #pragma unroll
            for (int j = 0; j < 8; j++) {
                uint32_t a[4];
                ldsm4(a, aFragRow + aOff + kOwn + j * 32);
                #pragma unroll
                for (int g = 0; g < 2; g++) {
                    uint32_t b[4];
                    ldsm4(b, bBase + (bRow0 + g * 16) * UROW + kOwn + j * 32);
                    mma_fp8(acc[2 * g],     a, b[0], b[1]);
                    mma_fp8(acc[2 * g + 1], a, b[2], b[3]);
                }
            }
            // wait for peer half, then finish
            mbar_wait_cluster(sb + SB_MBAR + (uint32_t)(t & 1) * 8,
                              (uint32_t)(((t - 1) >> 1) & 1));
            #pragma unroll
            for (int j = 0; j < 8; j++) {
                uint32_t a[4];
                ldsm4(a, aFragRow + aOff + kPeer + j * 32);
                #pragma unroll
                for (int g = 0; g < 2; g++) {
                    uint32_t b[4];
                    ldsm4(b, bBase + (bRow0 + g * 16) * UROW + kPeer + j * 32);
                    mma_fp8(acc[2 * g],     a, b[0], b[1]);
                    mma_fp8(acc[2 * g + 1], a, b[2], b[3]);
                }
            }
        }

        // epilogue: h = tanh(acc*DESCALE + XW); store fp8*HSCALE
        const uint32_t aNext = SB_A + (uint32_t)((t + 1) & 1) * RABUF;
        #pragma unroll
        for (int nf = 0; nf < 4; nf++) {
            float2 xa = __bfloat1622float2(*(__nv_bfloat162*)&xwv[nf][0]);
            float2 xb = __bfloat1622float2(*(__nv_bfloat162*)&xwv[nf][1]);
            float p0 = ftanh(acc[nf][0] * DESCALE + xa.x);
            float p1 = ftanh(acc[nf][1] * DESCALE + xa.y);
            float p2 = ftanh(acc[nf][2] * DESCALE + xb.x);
            float p3 = ftanh(acc[nf][3] * DESCALE + xb.y);
            unsigned short v0 = __nv_cvt_float2_to_fp8x2(
                make_float2(p0 * HSCALE, p1 * HSCALE), __NV_SATFINITE, __NV_E4M3);
            unsigned short v1 = __nv_cvt_float2_to_fp8x2(
                make_float2(p2 * HSCALE, p3 * HSCALE), __NV_SATFINITE, __NV_E4M3);
            const int colK = colBase + c0l + nf * 8;
            size_t gbase = ((size_t)t * BATCH + rowBase + r0l) * UNITS + colK;
            *(unsigned short*)(X + gbase)             = v0;   // global (next layer/head)
            *(unsigned short*)(X + gbase + 8 * UNITS) = v1;
            if (t < SEQ - 1) {
                uint32_t off0 = aNext + (uint32_t)r0l * UROW + colK;
                uint32_t off1 = off0 + 8 * UROW;
                asm volatile("st.shared.u16 [%0], %1;" :: "r"(sb + off0), "h"(v0));
                asm volatile("st.shared.u16 [%0], %1;" :: "r"(sb + off1), "h"(v1));
                asm volatile("st.shared::cluster.u16 [%0], %1;" :: "r"(peerSb + off0), "h"(v0));
                asm volatile("st.shared::cluster.u16 [%0], %1;" :: "r"(peerSb + off1), "h"(v1));
            }
        }

        if (t < SEQ - 1) {
            __syncthreads();                          // all stores happen-before arrive
            if (tid == 0) {
                asm volatile("fence.acq_rel.cluster;" ::: "memory");
                uint32_t bi = (uint32_t)((t + 1) & 1) * 8;
                asm volatile("mbarrier.arrive.shared.b64 _, [%0];"
                             :: "r"(sb + SB_MBAR + bi) : "memory");
                asm volatile("mbarrier.arrive.release.cluster.shared::cluster.b64 _, [%0];"
                             :: "r"(peerSb + SB_MBAR + bi) : "memory");
            }
        }
    }

    asm volatile("barrier.cluster.arrive.aligned;" ::: "memory");
    asm volatile("barrier.cluster.wait.aligned;" ::: "memory");
}

// ---------------- head ----------------
__global__ void final_kernel(const uint8_t* __restrict__ X,
                             const float* __restrict__ Wo, const float* __restrict__ bo,
                             float* __restrict__ out) {
    int gw   = (blockIdx.x * blockDim.x + threadIdx.x) >> 5;
    int lane = threadIdx.x & 31;
    if (gw >= BATCH) return;
    const uint8_t* h = X + ((size_t)(SEQ - 1) * BATCH + gw) * UNITS;
    float s = 0.0f;
    for (int k = lane; k < UNITS; k += 32) {
        __half_raw hr = __nv_cvt_fp8_to_halfraw(h[k], __NV_E4M3);
        s += __half2float(*(__half*)&hr) * Wo[k];
    }
    #pragma unroll
    for (int o = 16; o; o >>= 1) s += __shfl_xor_sync(0xffffffffu, s, o);
    if (lane == 0) out[gw] = 1.0f / (1.0f + expf(-(s * (1.0f / HSCALE) + bo[0])));
}

// ---------------- host ----------------
extern "C" void kernel_launch(void* const* d_in, const int* in_sizes, int n_in,
                              void* d_out, int out_size) {
    const int*   tokens = (const int*)d_in[0];
    const float* emb    = (const float*)d_in[1];
    const float* W[4]  = {(const float*)d_in[2], (const float*)d_in[5],
                          (const float*)d_in[8], (const float*)d_in[11]};
    const float* U[4]  = {(const float*)d_in[3], (const float*)d_in[6],
                          (const float*)d_in[9], (const float*)d_in[12]};
    const float* bv[4] = {(const float*)d_in[4], (const float*)d_in[7],
                          (const float*)d_in[10], (const float*)d_in[13]};
    const float* Wo = (const float*)d_in[14];
    const float* bo = (const float*)d_in[15];
    float* out = (float*)d_out;

    uint8_t *X0p, *Xp, *W1tp, *Wtp, *Utp;
    __nv_bfloat16* XWp;
    cudaGetSymbolAddress((void**)&X0p,  g_X0);
    cudaGetSymbolAddress((void**)&Xp,   g_X);
    cudaGetSymbolAddress((void**)&XWp,  g_XW);
    cudaGetSymbolAddress((void**)&W1tp, g_W1t);
    cudaGetSymbolAddress((void**)&Wtp,  g_Wt);
    cudaGetSymbolAddress((void**)&Utp,  g_Ut);

    cudaFuncSetAttribute(gemm_fp8, cudaFuncAttributeMaxDynamicSharedMemorySize, XW_SMEM);
    cudaFuncSetAttribute(rnn_fp8,  cudaFuncAttributeMaxDynamicSharedMemorySize, R_SMEM);

    // launch #1, #2: prep (launch #3 = gemm L1, launch #4 = rnn L1 for ncu)
    cvtAll_kernel<<<(512*128 + 7*512*512 + 255) / 256, 256>>>(
        W[0], W[1], W[2], W[3], U[0], U[1], U[2], U[3]);
    embed_kernel<<<(BT * EMBP + 255) / 256, 256>>>(tokens, emb);

    for (int l = 0; l < 4; l++) {
        if (l == 0) {
            gemm_fp8<<<dim3(UNITS / 128, BT / 128), 256, XW_SMEM>>>(
                X0p, EMBP, W1tp, EMBP, bv[0], XWp, 1);
        } else {
            gemm_fp8<<<dim3(UNITS / 128, BT / 128), 256, XW_SMEM>>>(
                Xp, UNITS, Wtp + (size_t)(l - 1) * UNITS * UNITS, UNITS,
                bv[l], XWp, 4);
        }
        rnn_fp8<<<128, 512, R_SMEM>>>(
            Utp + (size_t)l * UNITS * UNITS, XWp, Xp, l);
    }

    final_kernel<<<BATCH / 8, 256>>>(Xp, Wo, bo, out);
}